// round 15
// baseline (speedup 1.0000x reference)
#include <cuda_runtime.h>
#include <cuda_fp16.h>
#include <cstdint>

#define BB 4
#define SS 2048
#define EE 1024
#define HH 16
#define DD 64
#define MROWS (BB * SS)   // 8192
#define L2E 1.4426950408889634f

// Scratch (device globals: allocation-free rule). All fp16, 16B-aligned.
__device__ __align__(16) __half g_q[BB * HH * SS * DD];    // scaled 1/8, +bias
__device__ __align__(16) __half g_khi[BB * HH * SS * DD];  // fp16 hi of k (+bias)
__device__ __align__(16) __half g_klo[BB * HH * SS * DD];  // fp16 residual of k
__device__ __align__(16) __half g_v[BB * HH * SS * DD];    // v (+bias)
__device__ __align__(16) __half g_att[BB * SS * EE];       // attention out
__device__ __align__(16) __half g_xa[MROWS * EE];          // x
__device__ __align__(16) __half g_wqkv[3 * EE * EE];       // qkv_w
__device__ __align__(16) __half g_wout[EE * EE];           // out_w

// ---------------------------------------------------------------------------
__device__ __forceinline__ void mma16(float* c,
                                      uint32_t a0, uint32_t a1, uint32_t a2, uint32_t a3,
                                      uint32_t b0, uint32_t b1) {
    asm volatile(
        "mma.sync.aligned.m16n8k16.row.col.f32.f16.f16.f32 "
        "{%0,%1,%2,%3}, {%4,%5,%6,%7}, {%8,%9}, {%0,%1,%2,%3};"
        : "+f"(c[0]), "+f"(c[1]), "+f"(c[2]), "+f"(c[3])
        : "r"(a0), "r"(a1), "r"(a2), "r"(a3), "r"(b0), "r"(b1));
}

__device__ __forceinline__ void cpa16(uint32_t dst, const void* src) {
    asm volatile("cp.async.cg.shared.global [%0], [%1], 16;"
                 :: "r"(dst), "l"(src));
}
#define CP_COMMIT() asm volatile("cp.async.commit_group;" ::: "memory")
#define CP_WAIT(n)  asm volatile("cp.async.wait_group %0;" :: "n"(n) : "memory")

__device__ __forceinline__ uint32_t smem_u32(const void* p) {
    uint32_t a;
    asm("{ .reg .u64 t; cvta.to.shared.u64 t, %1; cvt.u32.u64 %0, t; }"
        : "=r"(a) : "l"(p));
    return a;
}

__device__ __forceinline__ void ldsm_x4(uint32_t& r0, uint32_t& r1,
                                        uint32_t& r2, uint32_t& r3,
                                        uint32_t addr) {
    asm volatile("ldmatrix.sync.aligned.m8n8.x4.shared.b16 "
                 "{%0,%1,%2,%3}, [%4];"
                 : "=r"(r0), "=r"(r1), "=r"(r2), "=r"(r3) : "r"(addr));
}

__device__ __forceinline__ void ldsm_x4_trans(uint32_t& r0, uint32_t& r1,
                                              uint32_t& r2, uint32_t& r3,
                                              uint32_t addr) {
    asm volatile("ldmatrix.sync.aligned.m8n8.x4.trans.shared.b16 "
                 "{%0,%1,%2,%3}, [%4];"
                 : "=r"(r0), "=r"(r1), "=r"(r2), "=r"(r3) : "r"(addr));
}

// fast exp2 on fma pipe (no MUFU bottleneck)
__device__ __forceinline__ float fexp2(float x) {
    x = fmaxf(x, -125.0f);
    const int ei = __float2int_rn(x);
    const float f = x - (float)ei;
    float p = fmaf(f, 0.0096181291f, 0.0555041087f);
    p = fmaf(f, p, 0.2402264923f);
    p = fmaf(f, p, 0.6931471806f);
    p = fmaf(f, p, 1.0f);
    return p * __int_as_float((ei + 127) << 23);
}

__device__ __forceinline__ uint32_t pack2(float lo, float hi) {
    __half2 h = __floats2half2_rn(lo, hi);
    return *(uint32_t*)&h;
}

// ---------------------------------------------------------------------------
// prep: round f32 array to fp16 scratch
// ---------------------------------------------------------------------------
__global__ __launch_bounds__(256) void cvt_kernel(const float4* __restrict__ src,
                                                  __half* __restrict__ dst, int n4)
{
    const int i = blockIdx.x * blockDim.x + threadIdx.x;
    if (i < n4) {
        float4 v = src[i];
        __half2* d = (__half2*)(dst + i * 4);
        d[0] = __floats2half2_rn(v.x, v.y);
        d[1] = __floats2half2_rn(v.z, v.w);
    }
}

// ===========================================================================
// fp16 mma.sync GEMM: C[M,N] = A[M,K=1024] @ W[N,K]^T + bias
// CTA 128x128, 8 warps (2x4) of 64x32, k-chunk 32 halves, 3-stage cp.async.
// Fragments via ldmatrix.x4 (rows stride 40 halves = 5 granules, odd ->
// conflict-free). MODE 0: -> g_q/g_khi+g_klo/g_v; MODE 1: -> Cp (f32) + bias.
// ===========================================================================
#define LDW 20                      // words per row
#define ASZW (128 * LDW)            // one stage A (words)
#define BSZW (128 * LDW)
#define NST 3
#define GEMM_SMEM (NST * (ASZW + BSZW) * 4)   // 61440 B

template <int MODE>
__global__ __launch_bounds__(256, 2) void gemm_mma(
    const float* __restrict__ bias, float* __restrict__ Cp, int N)
{
    extern __shared__ uint32_t sm[];
    const uint32_t sm_b = smem_u32(sm);

    const __half* A = (MODE == 1) ? g_att : g_xa;
    const __half* W = (MODE == 1) ? g_wout : g_wqkv;

    const int tid = threadIdx.x, lane = tid & 31, wid = tid >> 5;
    const int bm = blockIdx.y, bn = blockIdx.x;
    const int wm = wid >> 2, wn = wid & 3;
    const int gr = lane >> 2, tc = lane & 3;

    // ldmatrix per-lane geometry
    const int lm_row = lane & 15;
    const int lm_cw  = (lane >> 4) * 4;       // column offset in words (8 halves)

    // staging: f0 = tid (rows 0..63), f1 = tid + 256 (rows 64..127)
    const int f0 = tid, f1 = tid + 256;
    const __half* Ag0 = A + (size_t)(bm * 128 + (f0 >> 2)) * 1024 + (f0 & 3) * 8;
    const __half* Ag1 = A + (size_t)(bm * 128 + (f1 >> 2)) * 1024 + (f1 & 3) * 8;
    const __half* Wg0 = W + (size_t)(bn * 128 + (f0 >> 2)) * 1024 + (f0 & 3) * 8;
    const __half* Wg1 = W + (size_t)(bn * 128 + (f1 >> 2)) * 1024 + (f1 & 3) * 8;
    const uint32_t dA0 = sm_b + (((f0 >> 2) * LDW + (f0 & 3) * 4)) * 4;
    const uint32_t dA1 = sm_b + (((f1 >> 2) * LDW + (f1 & 3) * 4)) * 4;
    const uint32_t dB0 = dA0 + NST * ASZW * 4;
    const uint32_t dB1 = dA1 + NST * ASZW * 4;

    float acc[4][4][4];
#pragma unroll
    for (int i = 0; i < 4; ++i)
#pragma unroll
        for (int j = 0; j < 4; ++j)
#pragma unroll
            for (int t = 0; t < 4; ++t) acc[i][j][t] = 0.f;

#define ISSUE(stg, kt)                                                        \
    do {                                                                      \
        cpa16(dA0 + (stg) * ASZW * 4, Ag0 + (kt) * 32);                       \
        cpa16(dA1 + (stg) * ASZW * 4, Ag1 + (kt) * 32);                       \
        cpa16(dB0 + (stg) * BSZW * 4, Wg0 + (kt) * 32);                       \
        cpa16(dB1 + (stg) * BSZW * 4, Wg1 + (kt) * 32);                       \
        CP_COMMIT();                                                          \
    } while (0)

    ISSUE(0, 0);
    ISSUE(1, 1);

    for (int kt = 0; kt < 32; ++kt) {
        CP_WAIT(1);
        __syncthreads();

        const uint32_t aoff = sm_b + ((kt % NST) * ASZW) * 4;
        const uint32_t boff = sm_b + (NST * ASZW + (kt % NST) * BSZW) * 4;
#pragma unroll
        for (int kk = 0; kk < 2; ++kk) {
            uint32_t af[4][4], bf[4][2];
#pragma unroll
            for (int mi = 0; mi < 4; ++mi) {
                const uint32_t a = aoff +
                    ((wm * 64 + mi * 16 + lm_row) * LDW + kk * 8 + lm_cw) * 4;
                ldsm_x4(af[mi][0], af[mi][1], af[mi][2], af[mi][3], a);
            }
#pragma unroll
            for (int p = 0; p < 2; ++p) {
                uint32_t t0, t1, t2, t3;
                const uint32_t a = boff +
                    ((wn * 32 + p * 16 + lm_row) * LDW + kk * 8 + lm_cw) * 4;
                ldsm_x4(t0, t1, t2, t3, a);
                bf[2 * p][0] = t0;     bf[2 * p][1] = t2;
                bf[2 * p + 1][0] = t1; bf[2 * p + 1][1] = t3;
            }
#pragma unroll
            for (int mi = 0; mi < 4; ++mi)
#pragma unroll
                for (int ni = 0; ni < 4; ++ni)
                    mma16(acc[mi][ni], af[mi][0], af[mi][1], af[mi][2], af[mi][3],
                          bf[ni][0], bf[ni][1]);
        }
        __syncthreads();
        if (kt + 2 < 32) {
            ISSUE((kt + 2) % NST, kt + 2);
        } else {
            CP_COMMIT();
        }
    }
#undef ISSUE

    // ---------------- epilogue ----------------
    if (MODE == 1) {
#pragma unroll
        for (int mi = 0; mi < 4; ++mi)
#pragma unroll
            for (int rr = 0; rr < 2; ++rr) {
                const int row = bm * 128 + wm * 64 + mi * 16 + rr * 8 + gr;
#pragma unroll
                for (int ni = 0; ni < 4; ++ni) {
                    const int col = bn * 128 + wn * 32 + ni * 8 + 2 * tc;
                    float2 o;
                    o.x = acc[mi][ni][rr * 2]     + bias[col];
                    o.y = acc[mi][ni][rr * 2 + 1] + bias[col + 1];
                    *(float2*)(Cp + (size_t)row * N + col) = o;
                }
            }
    } else {
        // warp covers 32 cols inside one 64-col (head,part) group
        const int cgw = bn * 2 + (wn >> 1);     // 0..47
        const int h = cgw / 3, cpart = cgw % 3;
        const int d0 = (wn & 1) * 32;
        __half* dstb = (cpart == 0) ? g_q : (cpart == 1) ? g_khi : g_v;
#pragma unroll
        for (int mi = 0; mi < 4; ++mi)
#pragma unroll
            for (int rr = 0; rr < 2; ++rr) {
                const int row = bm * 128 + wm * 64 + mi * 16 + rr * 8 + gr;
                const int b = row >> 11, s = row & 2047;
                const size_t ro = ((size_t)(b * HH + h) * SS + s) << 6;
#pragma unroll
                for (int ni = 0; ni < 4; ++ni) {
                    const int col = bn * 128 + wn * 32 + ni * 8 + 2 * tc;
                    const int d = d0 + ni * 8 + 2 * tc;
                    float v0 = acc[mi][ni][rr * 2]     + bias[col];
                    float v1 = acc[mi][ni][rr * 2 + 1] + bias[col + 1];
                    if (cpart == 0) { v0 *= 0.125f; v1 *= 0.125f; }
                    __half2 hi2 = __floats2half2_rn(v0, v1);
                    *(uint32_t*)(dstb + ro + d) = *(uint32_t*)&hi2;
                    if (cpart == 1) {
                        float l0 = v0 - __half2float(__low2half(hi2));
                        float l1 = v1 - __half2float(__high2half(hi2));
                        __half2 lo2 = __floats2half2_rn(l0, l1);
                        *(uint32_t*)(g_klo + ro + d) = *(uint32_t*)&lo2;
                    }
                }
            }
    }
}

// ===========================================================================
// fp16 tensor-core causal flash attention.
// grid = (S/128, B*H), block = 128 (4 warps x m32), KV tile 64.
// P in registers; K frags via ldmatrix.x4 (stride 144B = 9 granules, odd ->
// conflict-free); V via ldmatrix.x4.trans. qt REVERSED: longest blocks first.
// ===========================================================================
#define KST 72
#define VSTH 88
#define ATTN_SMEM ((64 * KST * 2 + 64 * VSTH) * 2)   // 29696 B

__global__ __launch_bounds__(128, 2) void attn_mma()
{
    extern __shared__ __half smh[];
    __half* Khi = smh;                          // [64][KST]
    __half* Klo = smh + 64 * KST;
    __half* Vs  = smh + 128 * KST;              // [64][VSTH]
    const uint32_t khi_b = smem_u32(Khi);
    const uint32_t klo_b = smem_u32(Klo);
    const uint32_t vs_b  = smem_u32(Vs);

    const int tid = threadIdx.x, lane = tid & 31, wid = tid >> 5;
    const int gr = lane >> 2, tc = lane & 3;
    const int bh = blockIdx.y;
    const int qt = gridDim.x - 1 - blockIdx.x;   // longest-first scheduling
    const int qbase = qt * 128;
    const int wrow = qbase + wid * 32;

    const __half* Kh = g_khi + (size_t)bh * SS * DD;
    const __half* Kl = g_klo + (size_t)bh * SS * DD;
    const __half* Vg = g_v   + (size_t)bh * SS * DD;

    // ldmatrix per-lane geometry
    const int lm_row = lane & 15;
    const int lm_cw  = (lane >> 4) * 4;          // col offset in words
    const int lm_col = (lane >> 4) * 8;          // col offset in halves (V)

    // Q fragments in registers for the whole kernel: [mi][kk][4]
    uint32_t qa[2][4][4];
    {
        const uint32_t* Qw = (const uint32_t*)(g_q + ((size_t)bh * SS + wrow) * DD);
#pragma unroll
        for (int mi = 0; mi < 2; ++mi)
#pragma unroll
            for (int kk = 0; kk < 4; ++kk) {
                const int r0 = (mi * 16 + gr) * 32 + kk * 8 + tc;
                qa[mi][kk][0] = Qw[r0];
                qa[mi][kk][1] = Qw[r0 + 8 * 32];
                qa[mi][kk][2] = Qw[r0 + 4];
                qa[mi][kk][3] = Qw[r0 + 8 * 32 + 4];
            }
    }

    float Oc[2][8][4];
#pragma unroll
    for (int mi = 0; mi < 2; ++mi)
#pragma unroll
        for (int ni = 0; ni < 8; ++ni)
#pragma unroll
            for (int r = 0; r < 4; ++r) Oc[mi][ni][r] = 0.f;
    float mrow[2][2] = {{-1e30f, -1e30f}, {-1e30f, -1e30f}};
    float lrow[2][2] = {{0.f, 0.f}, {0.f, 0.f}};

    const int nkt = 2 * qt + 2;
    for (int kt = 0; kt < nkt; ++kt) {
        const int kvb = kt * 64;
        __syncthreads();

        // ---- cooperative copy (uint4, conflict-free) ----
#pragma unroll
        for (int j = 0; j < 4; ++j) {
            const int f = tid + j * 128;           // 0..511
            const int r = f >> 3, c = f & 7;
            *(uint4*)(Khi + r * KST + c * 8) = *(const uint4*)(Kh + (kvb + r) * DD + c * 8);
            *(uint4*)(Klo + r * KST + c * 8) = *(const uint4*)(Kl + (kvb + r) * DD + c * 8);
            *(uint4*)(Vs + r * VSTH + c * 8) = *(const uint4*)(Vg + (kvb + r) * DD + c * 8);
        }
        __syncthreads();

        if (kvb > wrow + 31) continue;

        // ---- QK^T (hi + lo split), K frags via ldmatrix ----
        float sc[2][8][4];
#pragma unroll
        for (int mi = 0; mi < 2; ++mi)
#pragma unroll
            for (int ni = 0; ni < 8; ++ni)
#pragma unroll
                for (int r = 0; r < 4; ++r) sc[mi][ni][r] = 0.f;

#pragma unroll
        for (int kk = 0; kk < 4; ++kk) {
            uint32_t bhv[8][2], blv[8][2];
#pragma unroll
            for (int p = 0; p < 4; ++p) {
                const uint32_t roff =
                    ((p * 16 + lm_row) * (KST / 2) + kk * 8 + lm_cw) * 4;
                uint32_t t0, t1, t2, t3;
                ldsm_x4(t0, t1, t2, t3, khi_b + roff);
                bhv[2 * p][0] = t0;     bhv[2 * p][1] = t2;
                bhv[2 * p + 1][0] = t1; bhv[2 * p + 1][1] = t3;
                ldsm_x4(t0, t1, t2, t3, klo_b + roff);
                blv[2 * p][0] = t0;     blv[2 * p][1] = t2;
                blv[2 * p + 1][0] = t1; blv[2 * p + 1][1] = t3;
            }
#pragma unroll
            for (int mi = 0; mi < 2; ++mi)
#pragma unroll
                for (int ni = 0; ni < 8; ++ni) {
                    mma16(sc[mi][ni], qa[mi][kk][0], qa[mi][kk][1],
                          qa[mi][kk][2], qa[mi][kk][3], bhv[ni][0], bhv[ni][1]);
                    mma16(sc[mi][ni], qa[mi][kk][0], qa[mi][kk][1],
                          qa[mi][kk][2], qa[mi][kk][3], blv[ni][0], blv[ni][1]);
                }
        }

        // ---- causal mask ----
        if (kvb + 63 > qbase) {
#pragma unroll
            for (int mi = 0; mi < 2; ++mi)
#pragma unroll
                for (int ni = 0; ni < 8; ++ni)
#pragma unroll
                    for (int r = 0; r < 4; ++r) {
                        const int i = wrow + mi * 16 + gr + (r >> 1) * 8;
                        const int j = kvb + ni * 8 + 2 * tc + (r & 1);
                        if (j > i) sc[mi][ni][r] = -1e30f;
                    }
        }

        // ---- online softmax; P packed to fp16 A-fragments in registers ----
        uint32_t pk[2][8][2];
#pragma unroll
        for (int mi = 0; mi < 2; ++mi)
#pragma unroll
            for (int rr = 0; rr < 2; ++rr) {
                float mx = -1e30f;
#pragma unroll
                for (int ni = 0; ni < 8; ++ni)
                    mx = fmaxf(mx, fmaxf(sc[mi][ni][rr * 2], sc[mi][ni][rr * 2 + 1]));
                mx = fmaxf(mx, __shfl_xor_sync(0xffffffffu, mx, 1));
                mx = fmaxf(mx, __shfl_xor_sync(0xffffffffu, mx, 2));
                const float mnew = fmaxf(mrow[mi][rr], mx);
                const float corr = fexp2((mrow[mi][rr] - mnew) * L2E);
                mrow[mi][rr] = mnew;
                const float mL = mnew * L2E;
                float rs = 0.f;
#pragma unroll
                for (int ni = 0; ni < 8; ++ni) {
                    const float p0 = fexp2(fmaf(sc[mi][ni][rr * 2],     L2E, -mL));
                    const float p1 = fexp2(fmaf(sc[mi][ni][rr * 2 + 1], L2E, -mL));
                    rs += p0 + p1;
                    Oc[mi][ni][rr * 2]     *= corr;
                    Oc[mi][ni][rr * 2 + 1] *= corr;
                    pk[mi][ni][rr] = pack2(p0, p1);
                }
                rs += __shfl_xor_sync(0xffffffffu, rs, 1);
                rs += __shfl_xor_sync(0xffffffffu, rs, 2);
                lrow[mi][rr] = lrow[mi][rr] * corr + rs;
            }

        // ---- PV: O += P @ V  (A = pk registers; B via ldmatrix.x4.trans) ----
#pragma unroll
        for (int kk = 0; kk < 4; ++kk) {
            uint32_t vb[8][2];
#pragma unroll
            for (int np = 0; np < 4; ++np) {
                const uint32_t addr = vs_b +
                    ((kk * 16 + lm_row) * VSTH + np * 16 + lm_col) * 2;
                ldsm_x4_trans(vb[2 * np][0], vb[2 * np][1],
                              vb[2 * np + 1][0], vb[2 * np + 1][1], addr);
            }
#pragma unroll
            for (int mi = 0; mi < 2; ++mi)
#pragma unroll
                for (int ni = 0; ni < 8; ++ni)
                    mma16(Oc[mi][ni],
                          pk[mi][2 * kk][0], pk[mi][2 * kk][1],
                          pk[mi][2 * kk + 1][0], pk[mi][2 * kk + 1][1],
                          vb[ni][0], vb[ni][1]);
        }
    }

    // ---- normalize + store fp16 to g_att [B,S,E] ----
    const int b = bh >> 4, hh = bh & 15;
#pragma unroll
    for (int mi = 0; mi < 2; ++mi)
#pragma unroll
        for (int rr = 0; rr < 2; ++rr) {
            const float inv = 1.0f / lrow[mi][rr];
            const int row = wrow + mi * 16 + rr * 8 + gr;
            __half* og = g_att + (size_t)(b * SS + row) * EE + hh * 64;
#pragma unroll
            for (int ni = 0; ni < 8; ++ni) {
                __half2 o = __floats2half2_rn(Oc[mi][ni][rr * 2] * inv,
                                              Oc[mi][ni][rr * 2 + 1] * inv);
                *(uint32_t*)(og + ni * 8 + 2 * tc) = *(uint32_t*)&o;
            }
        }
}

// ---------------------------------------------------------------------------
extern "C" void kernel_launch(void* const* d_in, const int* in_sizes, int n_in,
                              void* d_out, int out_size)
{
    const float* x     = (const float*)d_in[0];
    const float* qkv_w = (const float*)d_in[1];
    const float* qkv_b = (const float*)d_in[2];
    const float* out_w = (const float*)d_in[3];
    const float* out_b = (const float*)d_in[4];
    float* out = (float*)d_out;

    cudaFuncSetAttribute(gemm_mma<0>, cudaFuncAttributeMaxDynamicSharedMemorySize, GEMM_SMEM);
    cudaFuncSetAttribute(gemm_mma<1>, cudaFuncAttributeMaxDynamicSharedMemorySize, GEMM_SMEM);
    cudaFuncSetAttribute(attn_mma, cudaFuncAttributeMaxDynamicSharedMemorySize, ATTN_SMEM);

    __half* xa; __half* wq; __half* wo;
    cudaGetSymbolAddress((void**)&xa, g_xa);
    cudaGetSymbolAddress((void**)&wq, g_wqkv);
    cudaGetSymbolAddress((void**)&wo, g_wout);

    // 0) round inputs to fp16 scratch
    cvt_kernel<<<(MROWS * EE / 4 + 255) / 256, 256>>>((const float4*)x, xa, MROWS * EE / 4);
    cvt_kernel<<<(3 * EE * EE / 4 + 255) / 256, 256>>>((const float4*)qkv_w, wq, 3 * EE * EE / 4);
    cvt_kernel<<<(EE * EE / 4 + 255) / 256, 256>>>((const float4*)out_w, wo, EE * EE / 4);

    // 1) fused QKV projection -> g_q (scaled) / g_khi,g_klo / g_v (fp16)
    gemm_mma<0><<<dim3(3072 / 128, MROWS / 128), 256, GEMM_SMEM>>>(qkv_b, nullptr, 3 * EE);

    // 2) causal flash attention -> g_att (fp16)
    attn_mma<<<dim3(SS / 128, BB * HH), 128, ATTN_SMEM>>>();

    // 3) output projection -> d_out (f32)
    gemm_mma<1><<<dim3(EE / 128, MROWS / 128), 256, GEMM_SMEM>>>(out_b, out, EE);
}

// round 17
// speedup vs baseline: 1.1380x; 1.1380x over previous
#include <cuda_runtime.h>
#include <cuda_fp16.h>
#include <cstdint>

#define BB 4
#define SS 2048
#define EE 1024
#define HH 16
#define DD 64
#define MROWS (BB * SS)   // 8192
#define L2E 1.4426950408889634f

// Scratch (device globals: allocation-free rule). All fp16, 16B-aligned.
__device__ __align__(16) __half g_q[BB * HH * SS * DD];    // scaled 1/8, +bias
__device__ __align__(16) __half g_k[BB * HH * SS * DD];    // k (+bias)
__device__ __align__(16) __half g_v[BB * HH * SS * DD];    // v (+bias)
__device__ __align__(16) __half g_att[BB * SS * EE];       // attention out
__device__ __align__(16) __half g_xa[MROWS * EE];          // x
__device__ __align__(16) __half g_wqkv[3 * EE * EE];       // qkv_w
__device__ __align__(16) __half g_wout[EE * EE];           // out_w

// ---------------------------------------------------------------------------
__device__ __forceinline__ void mma16(float* c,
                                      uint32_t a0, uint32_t a1, uint32_t a2, uint32_t a3,
                                      uint32_t b0, uint32_t b1) {
    asm volatile(
        "mma.sync.aligned.m16n8k16.row.col.f32.f16.f16.f32 "
        "{%0,%1,%2,%3}, {%4,%5,%6,%7}, {%8,%9}, {%0,%1,%2,%3};"
        : "+f"(c[0]), "+f"(c[1]), "+f"(c[2]), "+f"(c[3])
        : "r"(a0), "r"(a1), "r"(a2), "r"(a3), "r"(b0), "r"(b1));
}

__device__ __forceinline__ void cpa16(uint32_t dst, const void* src) {
    asm volatile("cp.async.cg.shared.global [%0], [%1], 16;"
                 :: "r"(dst), "l"(src));
}
#define CP_COMMIT() asm volatile("cp.async.commit_group;" ::: "memory")
#define CP_WAIT(n)  asm volatile("cp.async.wait_group %0;" :: "n"(n) : "memory")

__device__ __forceinline__ uint32_t smem_u32(const void* p) {
    uint32_t a;
    asm("{ .reg .u64 t; cvta.to.shared.u64 t, %1; cvt.u32.u64 %0, t; }"
        : "=r"(a) : "l"(p));
    return a;
}

__device__ __forceinline__ void ldsm_x4_trans(uint32_t& r0, uint32_t& r1,
                                              uint32_t& r2, uint32_t& r3,
                                              uint32_t addr) {
    asm volatile("ldmatrix.sync.aligned.m8n8.x4.trans.shared.b16 "
                 "{%0,%1,%2,%3}, [%4];"
                 : "=r"(r0), "=r"(r1), "=r"(r2), "=r"(r3) : "r"(addr));
}

// fast exp2 on fma pipe (no MUFU bottleneck)
__device__ __forceinline__ float fexp2(float x) {
    x = fmaxf(x, -125.0f);
    const int ei = __float2int_rn(x);
    const float f = x - (float)ei;
    float p = fmaf(f, 0.0096181291f, 0.0555041087f);
    p = fmaf(f, p, 0.2402264923f);
    p = fmaf(f, p, 0.6931471806f);
    p = fmaf(f, p, 1.0f);
    return p * __int_as_float((ei + 127) << 23);
}

__device__ __forceinline__ uint32_t pack2(float lo, float hi) {
    __half2 h = __floats2half2_rn(lo, hi);
    return *(uint32_t*)&h;
}

// ---------------------------------------------------------------------------
// prep: round f32 array to fp16 scratch
// ---------------------------------------------------------------------------
__global__ __launch_bounds__(256) void cvt_kernel(const float4* __restrict__ src,
                                                  __half* __restrict__ dst, int n4)
{
    const int i = blockIdx.x * blockDim.x + threadIdx.x;
    if (i < n4) {
        float4 v = src[i];
        __half2* d = (__half2*)(dst + i * 4);
        d[0] = __floats2half2_rn(v.x, v.y);
        d[1] = __floats2half2_rn(v.z, v.w);
    }
}

// ===========================================================================
// fp16 mma.sync GEMM (R14 structure): C[M,N] = A[M,K=1024] @ W[N,K]^T + bias
// CTA 128x128, 8 warps (2x4) of 64x32, k-chunk 32 halves, 3-stage cp.async.
// smem rows stride 40 halves (20 words; conflict-free scalar fragment LDS).
// MODE 0: -> g_q (scaled) / g_k / g_v  (fp16)
// MODE 1: -> Cp (f32) with bias
// ===========================================================================
#define LDW 20                      // words per row
#define ASZW (128 * LDW)            // one stage A (words)
#define BSZW (128 * LDW)
#define NST 3
#define GEMM_SMEM (NST * (ASZW + BSZW) * 4)   // 61440 B

template <int MODE>
__global__ __launch_bounds__(256, 2) void gemm_mma(
    const float* __restrict__ bias, float* __restrict__ Cp, int N)
{
    extern __shared__ uint32_t sm[];
    const uint32_t sm_b = smem_u32(sm);

    const __half* A = (MODE == 1) ? g_att : g_xa;
    const __half* W = (MODE == 1) ? g_wout : g_wqkv;

    const int tid = threadIdx.x, lane = tid & 31, wid = tid >> 5;
    const int bm = blockIdx.y, bn = blockIdx.x;
    const int wm = wid >> 2, wn = wid & 3;
    const int gr = lane >> 2, tc = lane & 3;

    // staging: f0 = tid (rows 0..63), f1 = tid + 256 (rows 64..127)
    const int f0 = tid, f1 = tid + 256;
    const __half* Ag0 = A + (size_t)(bm * 128 + (f0 >> 2)) * 1024 + (f0 & 3) * 8;
    const __half* Ag1 = A + (size_t)(bm * 128 + (f1 >> 2)) * 1024 + (f1 & 3) * 8;
    const __half* Wg0 = W + (size_t)(bn * 128 + (f0 >> 2)) * 1024 + (f0 & 3) * 8;
    const __half* Wg1 = W + (size_t)(bn * 128 + (f1 >> 2)) * 1024 + (f1 & 3) * 8;
    const uint32_t dA0 = sm_b + (((f0 >> 2) * LDW + (f0 & 3) * 4)) * 4;
    const uint32_t dA1 = sm_b + (((f1 >> 2) * LDW + (f1 & 3) * 4)) * 4;
    const uint32_t dB0 = dA0 + NST * ASZW * 4;
    const uint32_t dB1 = dA1 + NST * ASZW * 4;

    float acc[4][4][4];
#pragma unroll
    for (int i = 0; i < 4; ++i)
#pragma unroll
        for (int j = 0; j < 4; ++j)
#pragma unroll
            for (int t = 0; t < 4; ++t) acc[i][j][t] = 0.f;

#define ISSUE(stg, kt)                                                        \
    do {                                                                      \
        cpa16(dA0 + (stg) * ASZW * 4, Ag0 + (kt) * 32);                       \
        cpa16(dA1 + (stg) * ASZW * 4, Ag1 + (kt) * 32);                       \
        cpa16(dB0 + (stg) * BSZW * 4, Wg0 + (kt) * 32);                       \
        cpa16(dB1 + (stg) * BSZW * 4, Wg1 + (kt) * 32);                       \
        CP_COMMIT();                                                          \
    } while (0)

    ISSUE(0, 0);
    ISSUE(1, 1);

    for (int kt = 0; kt < 32; ++kt) {
        CP_WAIT(1);
        __syncthreads();

        const uint32_t* as = sm + (kt % NST) * ASZW;
        const uint32_t* bs = sm + NST * ASZW + (kt % NST) * BSZW;
#pragma unroll
        for (int kk = 0; kk < 2; ++kk) {
            uint32_t af[4][4], bf[4][2];
#pragma unroll
            for (int mi = 0; mi < 4; ++mi) {
                const int rb = (wm * 64 + mi * 16 + gr) * LDW + kk * 8 + tc;
                af[mi][0] = as[rb];
                af[mi][1] = as[rb + 8 * LDW];
                af[mi][2] = as[rb + 4];
                af[mi][3] = as[rb + 8 * LDW + 4];
            }
#pragma unroll
            for (int ni = 0; ni < 4; ++ni) {
                const int cb = (wn * 32 + ni * 8 + gr) * LDW + kk * 8 + tc;
                bf[ni][0] = bs[cb];
                bf[ni][1] = bs[cb + 4];
            }
#pragma unroll
            for (int mi = 0; mi < 4; ++mi)
#pragma unroll
                for (int ni = 0; ni < 4; ++ni)
                    mma16(acc[mi][ni], af[mi][0], af[mi][1], af[mi][2], af[mi][3],
                          bf[ni][0], bf[ni][1]);
        }
        __syncthreads();
        if (kt + 2 < 32) {
            ISSUE((kt + 2) % NST, kt + 2);
        } else {
            CP_COMMIT();
        }
    }
#undef ISSUE

    // ---------------- epilogue ----------------
    if (MODE == 1) {
#pragma unroll
        for (int mi = 0; mi < 4; ++mi)
#pragma unroll
            for (int rr = 0; rr < 2; ++rr) {
                const int row = bm * 128 + wm * 64 + mi * 16 + rr * 8 + gr;
#pragma unroll
                for (int ni = 0; ni < 4; ++ni) {
                    const int col = bn * 128 + wn * 32 + ni * 8 + 2 * tc;
                    float2 o;
                    o.x = acc[mi][ni][rr * 2]     + bias[col];
                    o.y = acc[mi][ni][rr * 2 + 1] + bias[col + 1];
                    *(float2*)(Cp + (size_t)row * N + col) = o;
                }
            }
    } else {
        // warp covers 32 cols inside one 64-col (head,part) group
        const int cgw = bn * 2 + (wn >> 1);     // 0..47
        const int h = cgw / 3, cpart = cgw % 3;
        const int d0 = (wn & 1) * 32;
        __half* dstb = (cpart == 0) ? g_q : (cpart == 1) ? g_k : g_v;
#pragma unroll
        for (int mi = 0; mi < 4; ++mi)
#pragma unroll
            for (int rr = 0; rr < 2; ++rr) {
                const int row = bm * 128 + wm * 64 + mi * 16 + rr * 8 + gr;
                const int b = row >> 11, s = row & 2047;
                const size_t ro = ((size_t)(b * HH + h) * SS + s) << 6;
#pragma unroll
                for (int ni = 0; ni < 4; ++ni) {
                    const int col = bn * 128 + wn * 32 + ni * 8 + 2 * tc;
                    const int d = d0 + ni * 8 + 2 * tc;
                    float v0 = acc[mi][ni][rr * 2]     + bias[col];
                    float v1 = acc[mi][ni][rr * 2 + 1] + bias[col + 1];
                    if (cpart == 0) { v0 *= 0.125f; v1 *= 0.125f; }
                    __half2 hi2 = __floats2half2_rn(v0, v1);
                    *(uint32_t*)(dstb + ro + d) = *(uint32_t*)&hi2;
                }
            }
    }
}

// ===========================================================================
// fp16 tensor-core causal flash attention (no K split).
// grid = (S/128, B*H), block = 128 (4 warps x m32), KV tile 64.
// P in registers (C-frag -> A-frag identity). V via ldmatrix.x4.trans.
// qt reversed: longest blocks scheduled first.
// ===========================================================================
#define KST 72
#define VSTH 88
#define ATTN_SMEM ((64 * KST + 64 * VSTH) * 2)   // 20480 B

__global__ __launch_bounds__(128, 2) void attn_mma()
{
    extern __shared__ __half smh[];
    __half* Ks = smh;                           // [64][KST]
    __half* Vs = smh + 64 * KST;                // [64][VSTH]
    const uint32_t vs_b = smem_u32(Vs);

    const int tid = threadIdx.x, lane = tid & 31, wid = tid >> 5;
    const int gr = lane >> 2, tc = lane & 3;
    const int bh = blockIdx.y;
    const int qt = gridDim.x - 1 - blockIdx.x;   // longest-first scheduling
    const int qbase = qt * 128;
    const int wrow = qbase + wid * 32;

    const __half* Kg = g_k + (size_t)bh * SS * DD;
    const __half* Vg = g_v + (size_t)bh * SS * DD;

    // Q fragments in registers for the whole kernel: [mi][kk][4]
    uint32_t qa[2][4][4];
    {
        const uint32_t* Qw = (const uint32_t*)(g_q + ((size_t)bh * SS + wrow) * DD);
#pragma unroll
        for (int mi = 0; mi < 2; ++mi)
#pragma unroll
            for (int kk = 0; kk < 4; ++kk) {
                const int r0 = (mi * 16 + gr) * 32 + kk * 8 + tc;
                qa[mi][kk][0] = Qw[r0];
                qa[mi][kk][1] = Qw[r0 + 8 * 32];
                qa[mi][kk][2] = Qw[r0 + 4];
                qa[mi][kk][3] = Qw[r0 + 8 * 32 + 4];
            }
    }

    float Oc[2][8][4];
#pragma unroll
    for (int mi = 0; mi < 2; ++mi)
#pragma unroll
        for (int ni = 0; ni < 8; ++ni)
#pragma unroll
            for (int r = 0; r < 4; ++r) Oc[mi][ni][r] = 0.f;
    float mrow[2][2] = {{-1e30f, -1e30f}, {-1e30f, -1e30f}};
    float lrow[2][2] = {{0.f, 0.f}, {0.f, 0.f}};

    const int lm_row = lane & 15;
    const int lm_col = (lane >> 4) * 8;

    const int nkt = 2 * qt + 2;
    for (int kt = 0; kt < nkt; ++kt) {
        const int kvb = kt * 64;
        __syncthreads();

        // ---- cooperative copy (uint4, conflict-free) ----
#pragma unroll
        for (int j = 0; j < 4; ++j) {
            const int f = tid + j * 128;           // 0..511
            const int r = f >> 3, c = f & 7;
            *(uint4*)(Ks + r * KST + c * 8) = *(const uint4*)(Kg + (kvb + r) * DD + c * 8);
            *(uint4*)(Vs + r * VSTH + c * 8) = *(const uint4*)(Vg + (kvb + r) * DD + c * 8);
        }
        __syncthreads();

        if (kvb > wrow + 31) continue;

        // ---- QK^T ----
        float sc[2][8][4];
#pragma unroll
        for (int mi = 0; mi < 2; ++mi)
#pragma unroll
            for (int ni = 0; ni < 8; ++ni)
#pragma unroll
                for (int r = 0; r < 4; ++r) sc[mi][ni][r] = 0.f;

        const uint32_t* KsW = (const uint32_t*)Ks;
#pragma unroll
        for (int kk = 0; kk < 4; ++kk) {
            uint32_t bv[8][2];
#pragma unroll
            for (int ni = 0; ni < 8; ++ni) {
                const int ba = (ni * 8 + gr) * (KST / 2) + kk * 8 + tc;
                bv[ni][0] = KsW[ba]; bv[ni][1] = KsW[ba + 4];
            }
#pragma unroll
            for (int mi = 0; mi < 2; ++mi)
#pragma unroll
                for (int ni = 0; ni < 8; ++ni)
                    mma16(sc[mi][ni], qa[mi][kk][0], qa[mi][kk][1],
                          qa[mi][kk][2], qa[mi][kk][3], bv[ni][0], bv[ni][1]);
        }

        // ---- causal mask ----
        if (kvb + 63 > qbase) {
#pragma unroll
            for (int mi = 0; mi < 2; ++mi)
#pragma unroll
                for (int ni = 0; ni < 8; ++ni)
#pragma unroll
                    for (int r = 0; r < 4; ++r) {
                        const int i = wrow + mi * 16 + gr + (r >> 1) * 8;
                        const int j = kvb + ni * 8 + 2 * tc + (r & 1);
                        if (j > i) sc[mi][ni][r] = -1e30f;
                    }
        }

        // ---- online softmax; P packed to fp16 A-fragments in registers ----
        uint32_t pk[2][8][2];
#pragma unroll
        for (int mi = 0; mi < 2; ++mi)
#pragma unroll
            for (int rr = 0; rr < 2; ++rr) {
                float mx = -1e30f;
#pragma unroll
                for (int ni = 0; ni < 8; ++ni)
                    mx = fmaxf(mx, fmaxf(sc[mi][ni][rr * 2], sc[mi][ni][rr * 2 + 1]));
                mx = fmaxf(mx, __shfl_xor_sync(0xffffffffu, mx, 1));
                mx = fmaxf(mx, __shfl_xor_sync(0xffffffffu, mx, 2));
                const float mnew = fmaxf(mrow[mi][rr], mx);
                const float corr = fexp2((mrow[mi][rr] - mnew) * L2E);
                mrow[mi][rr] = mnew;
                const float mL = mnew * L2E;
                float rs = 0.f;
#pragma unroll
                for (int ni = 0; ni < 8; ++ni) {
                    const float p0 = fexp2(fmaf(sc[mi][ni][rr * 2],     L2E, -mL));
                    const float p1 = fexp2(fmaf(sc[mi][ni][rr * 2 + 1], L2E, -mL));
                    rs += p0 + p1;
                    Oc[mi][ni][rr * 2]     *= corr;
                    Oc[mi][ni][rr * 2 + 1] *= corr;
                    pk[mi][ni][rr] = pack2(p0, p1);
                }
                rs += __shfl_xor_sync(0xffffffffu, rs, 1);
                rs += __shfl_xor_sync(0xffffffffu, rs, 2);
                lrow[mi][rr] = lrow[mi][rr] * corr + rs;
            }

        // ---- PV: O += P @ V  (A = pk registers; B via ldmatrix.x4.trans) ----
#pragma unroll
        for (int kk = 0; kk < 4; ++kk) {
            uint32_t vb[8][2];
#pragma unroll
            for (int np = 0; np < 4; ++np) {
                const uint32_t addr = vs_b +
                    ((kk * 16 + lm_row) * VSTH + np * 16 + lm_col) * 2;
                ldsm_x4_trans(vb[2 * np][0], vb[2 * np][1],
                              vb[2 * np + 1][0], vb[2 * np + 1][1], addr);
            }
#pragma unroll
            for (int mi = 0; mi < 2; ++mi)
#pragma unroll
                for (int ni = 0; ni < 8; ++ni)
                    mma16(Oc[mi][ni],
                          pk[mi][2 * kk][0], pk[mi][2 * kk][1],
                          pk[mi][2 * kk + 1][0], pk[mi][2 * kk + 1][1],
                          vb[ni][0], vb[ni][1]);
        }
    }

    // ---- normalize + store fp16 to g_att [B,S,E] ----
    const int b = bh >> 4, hh = bh & 15;
#pragma unroll
    for (int mi = 0; mi < 2; ++mi)
#pragma unroll
        for (int rr = 0; rr < 2; ++rr) {
            const float inv = 1.0f / lrow[mi][rr];
            const int row = wrow + mi * 16 + rr * 8 + gr;
            __half* og = g_att + (size_t)(b * SS + row) * EE + hh * 64;
#pragma unroll
            for (int ni = 0; ni < 8; ++ni) {
                __half2 o = __floats2half2_rn(Oc[mi][ni][rr * 2] * inv,
                                              Oc[mi][ni][rr * 2 + 1] * inv);
                *(uint32_t*)(og + ni * 8 + 2 * tc) = *(uint32_t*)&o;
            }
        }
}

// ---------------------------------------------------------------------------
extern "C" void kernel_launch(void* const* d_in, const int* in_sizes, int n_in,
                              void* d_out, int out_size)
{
    const float* x     = (const float*)d_in[0];
    const float* qkv_w = (const float*)d_in[1];
    const float* qkv_b = (const float*)d_in[2];
    const float* out_w = (const float*)d_in[3];
    const float* out_b = (const float*)d_in[4];
    float* out = (float*)d_out;

    cudaFuncSetAttribute(gemm_mma<0>, cudaFuncAttributeMaxDynamicSharedMemorySize, GEMM_SMEM);
    cudaFuncSetAttribute(gemm_mma<1>, cudaFuncAttributeMaxDynamicSharedMemorySize, GEMM_SMEM);
    cudaFuncSetAttribute(attn_mma, cudaFuncAttributeMaxDynamicSharedMemorySize, ATTN_SMEM);

    __half* xa; __half* wq; __half* wo;
    cudaGetSymbolAddress((void**)&xa, g_xa);
    cudaGetSymbolAddress((void**)&wq, g_wqkv);
    cudaGetSymbolAddress((void**)&wo, g_wout);

    // 0) round inputs to fp16 scratch
    cvt_kernel<<<(MROWS * EE / 4 + 255) / 256, 256>>>((const float4*)x, xa, MROWS * EE / 4);
    cvt_kernel<<<(3 * EE * EE / 4 + 255) / 256, 256>>>((const float4*)qkv_w, wq, 3 * EE * EE / 4);
    cvt_kernel<<<(EE * EE / 4 + 255) / 256, 256>>>((const float4*)out_w, wo, EE * EE / 4);

    // 1) fused QKV projection -> g_q (scaled) / g_k / g_v (fp16)
    gemm_mma<0><<<dim3(3072 / 128, MROWS / 128), 256, GEMM_SMEM>>>(qkv_b, nullptr, 3 * EE);

    // 2) causal flash attention -> g_att (fp16)
    attn_mma<<<dim3(SS / 128, BB * HH), 128, ATTN_SMEM>>>();

    // 3) output projection -> d_out (f32)
    gemm_mma<1><<<dim3(EE / 128, MROWS / 128), 256, GEMM_SMEM>>>(out_b, out, EE);
}